// round 7
// baseline (speedup 1.0000x reference)
#include <cuda_runtime.h>
#include <math.h>

#define B_   2048
#define S_   61
#define D_   768
#define H_   512
#define L_   23
#define MTOT (B_ * S_)   // 124928 = 976 * 128 exactly

#define HEAD_TOK 1
#define TAIL_TOK 2

// Gate values g[b,k] (scratch; __device__ global, no allocation)
__device__ float g_buf[MTOT];

// ---------------------------------------------------------------------------
// Kernel 1: fused gate GEMM
//   g[r] = fc2_w . tanh(fc1_w @ V[r] + fc1_b) + fc2_b   for r = b*61+k
// GEMM M=124928, N=512, K=768. Block: BM=128 rows x (4 chunks of BN=128),
// BK=16, 256 threads, 8x8 micro-tiles.
// ---------------------------------------------------------------------------
#define BM  128
#define BN  128
#define BK  16
#define PAD 4

__global__ __launch_bounds__(256, 2)
void gate_kernel(const float* __restrict__ V,    // [MTOT][768]
                 const float* __restrict__ W1,   // [512][768]
                 const float* __restrict__ B1,   // [512]
                 const float* __restrict__ W2,   // [512]  (fc2_w is [1][512])
                 const float* __restrict__ B2)   // [1]
{
    __shared__ float As[BK][BM + PAD];
    __shared__ float Bs[BK][BN + PAD];
    __shared__ float gsh[BM];

    const int tid  = threadIdx.x;
    const int row0 = blockIdx.x * BM;
    const int ty   = tid >> 4;   // 0..15  row group (8 rows each)
    const int tx   = tid & 15;   // 0..15  col group (8 cols each)

    if (tid < BM) gsh[tid] = 0.0f;
    __syncthreads();

    #pragma unroll 1
    for (int nc = 0; nc < H_ / BN; ++nc) {
        const int n0 = nc * BN;

        float acc[8][8];
        #pragma unroll
        for (int i = 0; i < 8; ++i)
            #pragma unroll
            for (int j = 0; j < 8; ++j) acc[i][j] = 0.0f;

        #pragma unroll 1
        for (int k0 = 0; k0 < D_; k0 += BK) {
            // ---- load A tile (V rows), transposed into As[k][m] ----
            #pragma unroll
            for (int it = 0; it < 2; ++it) {
                int r = tid + it * 256;           // 0..511
                int m = r >> 2;
                int q = (r & 3) * 4;
                float4 v = *reinterpret_cast<const float4*>(
                    V + (size_t)(row0 + m) * D_ + k0 + q);
                As[q + 0][m] = v.x; As[q + 1][m] = v.y;
                As[q + 2][m] = v.z; As[q + 3][m] = v.w;
            }
            // ---- load B tile (fc1_w rows), transposed into Bs[k][n] ----
            #pragma unroll
            for (int it = 0; it < 2; ++it) {
                int r = tid + it * 256;
                int n = r >> 2;
                int q = (r & 3) * 4;
                float4 v = *reinterpret_cast<const float4*>(
                    W1 + (size_t)(n0 + n) * D_ + k0 + q);
                Bs[q + 0][n] = v.x; Bs[q + 1][n] = v.y;
                Bs[q + 2][n] = v.z; Bs[q + 3][n] = v.w;
            }
            __syncthreads();

            #pragma unroll
            for (int kk = 0; kk < BK; ++kk) {
                float a[8], b[8];
                *reinterpret_cast<float4*>(a)     = *reinterpret_cast<const float4*>(&As[kk][ty * 8]);
                *reinterpret_cast<float4*>(a + 4) = *reinterpret_cast<const float4*>(&As[kk][ty * 8 + 4]);
                *reinterpret_cast<float4*>(b)     = *reinterpret_cast<const float4*>(&Bs[kk][tx * 8]);
                *reinterpret_cast<float4*>(b + 4) = *reinterpret_cast<const float4*>(&Bs[kk][tx * 8 + 4]);
                #pragma unroll
                for (int i = 0; i < 8; ++i)
                    #pragma unroll
                    for (int j = 0; j < 8; ++j)
                        acc[i][j] = fmaf(a[i], b[j], acc[i][j]);
            }
            __syncthreads();
        }

        // ---- epilogue: tanh + fc2 dot, reduce across the 16 col-groups ----
        float gpart[8];
        #pragma unroll
        for (int i = 0; i < 8; ++i) gpart[i] = 0.0f;

        #pragma unroll
        for (int j = 0; j < 8; ++j) {
            int n   = n0 + tx * 8 + j;
            float w = W2[n];
            float c = B1[n];
            #pragma unroll
            for (int i = 0; i < 8; ++i)
                gpart[i] = fmaf(w, tanhf(acc[i][j] + c), gpart[i]);
        }
        // lanes 0..15 / 16..31 of each warp are the 16 tx values of one ty
        #pragma unroll
        for (int i = 0; i < 8; ++i) {
            float v = gpart[i];
            v += __shfl_xor_sync(0xffffffffu, v, 8);
            v += __shfl_xor_sync(0xffffffffu, v, 4);
            v += __shfl_xor_sync(0xffffffffu, v, 2);
            v += __shfl_xor_sync(0xffffffffu, v, 1);
            if (tx == 0) gsh[ty * 8 + i] += v;   // unique (ty,i) per thread -> no race
        }
        __syncthreads();
    }

    if (tid < BM)
        g_buf[row0 + tid] = gsh[tid] + B2[0];
}

// ---------------------------------------------------------------------------
// Kernel 2: per-batch attention + entity gather + classifier.
// Uses ms == 1/61 (softmax row-sum identity) to skip the first softmax.
// One block (256 threads) per batch.
// ---------------------------------------------------------------------------
__global__ __launch_bounds__(256)
void attn_kernel(const float* __restrict__ T,      // [B][61][768]
                 const float* __restrict__ V,      // [B][61][768]
                 const int*   __restrict__ ids,    // [B][61]
                 const float* __restrict__ CW,     // [23][1536]
                 const float* __restrict__ CB,     // [23]
                 float*       __restrict__ out)    // [B][23]
{
    const int b   = blockIdx.x;
    const int tid = threadIdx.x;
    const int warp = tid >> 5, lane = tid & 31;

    __shared__ int   hidx, tidx;
    __shared__ float Th[D_], Tt[D_];
    __shared__ float sc_h[S_ + 3], sc_t[S_ + 3], gs[S_ + 3];
    __shared__ float wh[S_ + 3], wt[S_ + 3];
    __shared__ float ent[2 * D_];

    if (tid == 0) { hidx = 0; tidx = 0; }
    __syncthreads();

    if (tid < S_) {
        int id = ids[b * S_ + tid];
        if (id == HEAD_TOK) hidx = tid;   // exactly one per row
        if (id == TAIL_TOK) tidx = tid;
        gs[tid] = g_buf[b * S_ + tid];
    }
    __syncthreads();

    const int hq = hidx, tq = tidx;
    for (int d = tid; d < D_; d += 256) {
        Th[d] = T[((size_t)b * S_ + hq) * D_ + d];
        Tt[d] = T[((size_t)b * S_ + tq) * D_ + d];
    }
    __syncthreads();

    // ---- raw scores for the two needed query rows ----
    for (int k = warp; k < S_; k += 8) {
        const float* vk = V + ((size_t)b * S_ + k) * D_;
        float sh = 0.0f, st = 0.0f;
        for (int d = lane; d < D_; d += 32) {
            float v = vk[d];
            sh = fmaf(Th[d], v, sh);
            st = fmaf(Tt[d], v, st);
        }
        #pragma unroll
        for (int o = 16; o; o >>= 1) {
            sh += __shfl_xor_sync(0xffffffffu, sh, o);
            st += __shfl_xor_sync(0xffffffffu, st, o);
        }
        if (lane == 0) { sc_h[k] = sh; sc_t[k] = st; }
    }
    __syncthreads();

    // ---- gated softmax: a = (scores*(1-g) + g/61) / sqrt(768) ----
    if (warp < 2) {
        const float* sc = warp ? sc_t : sc_h;
        float*       w  = warp ? wt   : wh;
        const float scale = sqrtf((float)D_);
        const float inv61 = 1.0f / (float)S_;

        int k0 = lane, k1 = lane + 32;
        float a0 = -1e30f, a1 = -1e30f;
        if (k0 < S_) a0 = (sc[k0] * (1.0f - gs[k0]) + gs[k0] * inv61) / scale;
        if (k1 < S_) a1 = (sc[k1] * (1.0f - gs[k1]) + gs[k1] * inv61) / scale;
        float m = fmaxf(a0, a1);
        #pragma unroll
        for (int o = 16; o; o >>= 1) m = fmaxf(m, __shfl_xor_sync(0xffffffffu, m, o));
        float e0 = (k0 < S_) ? expf(a0 - m) : 0.0f;
        float e1 = (k1 < S_) ? expf(a1 - m) : 0.0f;
        float s = e0 + e1;
        #pragma unroll
        for (int o = 16; o; o >>= 1) s += __shfl_xor_sync(0xffffffffu, s, o);
        float inv = 1.0f / s;
        if (k0 < S_) w[k0] = e0 * inv;
        if (k1 < S_) w[k1] = e1 * inv;
    }
    __syncthreads();

    // ---- out rows (entity vector): weighted sum over V keys ----
    for (int d = tid; d < D_; d += 256) {
        float ah = 0.0f, at = 0.0f;
        const float* vb = V + (size_t)b * S_ * D_ + d;
        #pragma unroll 4
        for (int k = 0; k < S_; ++k) {
            float v = vb[(size_t)k * D_];
            ah = fmaf(wh[k], v, ah);
            at = fmaf(wt[k], v, at);
        }
        ent[d]      = ah;
        ent[D_ + d] = at;
    }
    __syncthreads();

    // ---- classifier: logits[l] = clf_w[l] . entity + clf_b[l] ----
    for (int l = warp; l < L_; l += 8) {
        const float* cw = CW + (size_t)l * (2 * D_);
        float s = 0.0f;
        for (int d = lane; d < 2 * D_; d += 32)
            s = fmaf(cw[d], ent[d], s);
        #pragma unroll
        for (int o = 16; o; o >>= 1) s += __shfl_xor_sync(0xffffffffu, s, o);
        if (lane == 0) out[(size_t)b * L_ + l] = s + CB[l];
    }
}

// ---------------------------------------------------------------------------
extern "C" void kernel_launch(void* const* d_in, const int* in_sizes, int n_in,
                              void* d_out, int out_size)
{
    const float* T_recon = (const float*)d_in[0];
    const float* V_recon = (const float*)d_in[1];
    const int*   ids     = (const int*)  d_in[2];
    const float* fc1_w   = (const float*)d_in[3];
    const float* fc1_b   = (const float*)d_in[4];
    const float* fc2_w   = (const float*)d_in[5];
    const float* fc2_b   = (const float*)d_in[6];
    const float* clf_w   = (const float*)d_in[7];
    const float* clf_b   = (const float*)d_in[8];
    float* out = (float*)d_out;

    gate_kernel<<<MTOT / BM, 256>>>(V_recon, fc1_w, fc1_b, fc2_w, fc2_b);
    attn_kernel<<<B_, 256>>>(T_recon, V_recon, ids, clf_w, clf_b, out);
}

// round 13
// speedup vs baseline: 2.0028x; 2.0028x over previous
#include <cuda_runtime.h>
#include <cuda_bf16.h>
#include <math.h>
#include <stdint.h>

#define B_   2048
#define S_   61
#define D_   768
#define H_   512
#define L_   23
#define MTOT (B_ * S_)   // 124928 = 976 * 128

#define HEAD_TOK 1
#define TAIL_TOK 2

// ---------------- scratch globals (no allocation allowed) -------------------
__device__ float         g_buf[MTOT];
__device__ __nv_bfloat16 W1hi[H_ * D_];
__device__ __nv_bfloat16 W1lo[H_ * D_];

// ---------------- helpers ----------------------------------------------------
__device__ __forceinline__ uint32_t smem_u32(const void* p) {
    uint32_t a;
    asm("{ .reg .u64 t; cvta.to.shared.u64 t, %1; cvt.u32.u64 %0, t; }"
        : "=r"(a) : "l"(p));
    return a;
}
__device__ __forceinline__ void cp16(uint32_t dst, const void* src) {
    asm volatile("cp.async.cg.shared.global [%0], [%1], 16;"
                 :: "r"(dst), "l"(src) : "memory");
}
__device__ __forceinline__ void ldsm4(uint32_t* d, uint32_t addr) {
    asm volatile("ldmatrix.sync.aligned.m8n8.x4.shared.b16 {%0,%1,%2,%3}, [%4];"
                 : "=r"(d[0]), "=r"(d[1]), "=r"(d[2]), "=r"(d[3]) : "r"(addr));
}
__device__ __forceinline__ void mma16816(float* c, const uint32_t* a,
                                         uint32_t b0, uint32_t b1) {
    asm volatile(
        "mma.sync.aligned.m16n8k16.row.col.f32.bf16.bf16.f32 "
        "{%0,%1,%2,%3}, {%4,%5,%6,%7}, {%8,%9}, {%0,%1,%2,%3};"
        : "+f"(c[0]), "+f"(c[1]), "+f"(c[2]), "+f"(c[3])
        : "r"(a[0]), "r"(a[1]), "r"(a[2]), "r"(a[3]), "r"(b0), "r"(b1));
}

// ---------------------------------------------------------------------------
// prep_kernel: split W1 fp32 -> bf16 hi/lo
// ---------------------------------------------------------------------------
__global__ void prep_kernel(const float* __restrict__ W1) {
    int i = blockIdx.x * 256 + threadIdx.x;          // over H_*D_/4 float4s
    float4 x = reinterpret_cast<const float4*>(W1)[i];
    float v[4] = {x.x, x.y, x.z, x.w};
    unsigned short hs[4], ls[4];
#pragma unroll
    for (int j = 0; j < 4; ++j) {
        __nv_bfloat16 h = __float2bfloat16(v[j]);
        __nv_bfloat16 l = __float2bfloat16(v[j] - __bfloat162float(h));
        hs[j] = __bfloat16_as_ushort(h);
        ls[j] = __bfloat16_as_ushort(l);
    }
    uint2 hp = make_uint2((uint32_t)hs[0] | ((uint32_t)hs[1] << 16),
                          (uint32_t)hs[2] | ((uint32_t)hs[3] << 16));
    uint2 lp = make_uint2((uint32_t)ls[0] | ((uint32_t)ls[1] << 16),
                          (uint32_t)ls[2] | ((uint32_t)ls[3] << 16));
    *reinterpret_cast<uint2*>(&W1hi[4 * (size_t)i]) = hp;
    *reinterpret_cast<uint2*>(&W1lo[4 * (size_t)i]) = lp;
}

// ---------------------------------------------------------------------------
// gate_kernel: HMMA (mma.sync bf16, 3-pass hi/lo split) fused gate GEMM
//   H[128,512] = Vtile[128,768] @ W1^T ; g = w2 . tanh(H + b1) + b2
// CTA: 128 rows, 4 N-chunks of 128, BK=64 double-buffered. 8 warps (2m x 4n),
// warp tile m64 x n32 (4 m-tiles x 4 n-tiles of m16n8k16).
// ---------------------------------------------------------------------------
#define RS      144                  // smem row stride bytes (64 bf16 + 16B pad)
#define ABYTES  (128 * RS)           // 18432 per matrix
#define BUFB    (4 * ABYTES)         // Ahi, Alo, Bhi, Blo = 73728 per stage
#define OFF_W2  0
#define OFF_B1  2048
#define OFF_GS  4096                 // 512 floats (4 x 128)
#define OFF_BUF 8192
#define GATE_SMEM (OFF_BUF + 2 * BUFB)   // 155648

__global__ __launch_bounds__(256, 1)
void gate_kernel(const float* __restrict__ V,
                 const float* __restrict__ B1,
                 const float* __restrict__ W2,
                 const float* __restrict__ B2)
{
    extern __shared__ char sm[];
    const uint32_t sb = smem_u32(sm);
    const int tid  = threadIdx.x;
    const int wid  = tid >> 5;
    const int lane = tid & 31;
    const int wm   = wid >> 2;       // 0..1  (m direction)
    const int wn   = wid & 3;        // 0..3  (n direction)
    const int row0 = blockIdx.x * 128;

    float* w2s = reinterpret_cast<float*>(sm + OFF_W2);
    float* b1s = reinterpret_cast<float*>(sm + OFF_B1);
    float* gs  = reinterpret_cast<float*>(sm + OFF_GS);

    for (int i = tid; i < H_; i += 256) { w2s[i] = W2[i]; b1s[i] = B1[i]; }
    for (int i = tid; i < 512; i += 256) gs[i] = 0.0f;
    __syncthreads();

    // ldmatrix per-thread address components
    const int a_m  = (lane & 7) + ((lane >> 3) & 1) * 8;
    const int a_k2 = (lane >> 4) * 16;
    const int b_n  = (lane & 7) + (lane >> 4) * 8;
    const int b_k2 = ((lane >> 3) & 1) * 16;
    const uint32_t aoff = (uint32_t)((wm * 64 + a_m) * RS) + (uint32_t)a_k2;
    const uint32_t boff = (uint32_t)((wn * 32 + b_n) * RS) + (uint32_t)b_k2;

    float4 areg[8];

#pragma unroll 1
    for (int nc = 0; nc < 4; ++nc) {
        float c[4][4][4];
#pragma unroll
        for (int mt = 0; mt < 4; ++mt)
#pragma unroll
            for (int nt = 0; nt < 4; ++nt)
#pragma unroll
                for (int e = 0; e < 4; ++e) c[mt][nt][e] = 0.0f;

        // ---- prologue: load stage 0 ----
        {
            const int k0 = 0, n0 = nc * 128;
#pragma unroll
            for (int it = 0; it < 4; ++it) {
                int v = tid + it * 256, r = v >> 3, j = v & 7;
                uint32_t d = sb + OFF_BUF + 2u * ABYTES + (uint32_t)(r * RS + j * 16);
                cp16(d,                     W1hi + (size_t)(n0 + r) * D_ + k0 + j * 8);
                cp16(d + (uint32_t)ABYTES,  W1lo + (size_t)(n0 + r) * D_ + k0 + j * 8);
            }
            asm volatile("cp.async.commit_group;" ::: "memory");
#pragma unroll
            for (int it = 0; it < 8; ++it) {
                int v = tid + it * 256, r = v >> 4, c4 = v & 15;
                areg[it] = *reinterpret_cast<const float4*>(
                    V + (size_t)(row0 + r) * D_ + k0 + c4 * 4);
            }
#pragma unroll
            for (int it = 0; it < 8; ++it) {
                int v = tid + it * 256, r = v >> 4, c4 = v & 15;
                float f[4] = {areg[it].x, areg[it].y, areg[it].z, areg[it].w};
                unsigned short hs[4], ls[4];
#pragma unroll
                for (int j = 0; j < 4; ++j) {
                    __nv_bfloat16 h = __float2bfloat16(f[j]);
                    __nv_bfloat16 l = __float2bfloat16(f[j] - __bfloat162float(h));
                    hs[j] = __bfloat16_as_ushort(h); ls[j] = __bfloat16_as_ushort(l);
                }
                uint2 hp = make_uint2((uint32_t)hs[0] | ((uint32_t)hs[1] << 16),
                                      (uint32_t)hs[2] | ((uint32_t)hs[3] << 16));
                uint2 lp = make_uint2((uint32_t)ls[0] | ((uint32_t)ls[1] << 16),
                                      (uint32_t)ls[2] | ((uint32_t)ls[3] << 16));
                char* base = sm + OFF_BUF + r * RS + c4 * 8;
                *reinterpret_cast<uint2*>(base)          = hp;
                *reinterpret_cast<uint2*>(base + ABYTES) = lp;
            }
            asm volatile("cp.async.wait_group 0;" ::: "memory");
            __syncthreads();
        }

        // ---- main loop over 12 K-stages ----
#pragma unroll 1
        for (int s = 0; s < 12; ++s) {
            const uint32_t curOff = OFF_BUF + (uint32_t)(s & 1) * BUFB;
            const uint32_t nxtOff = OFF_BUF + (uint32_t)((s + 1) & 1) * BUFB;

            if (s < 11) {
                const int k0 = (s + 1) * 64, n0 = nc * 128;
#pragma unroll
                for (int it = 0; it < 4; ++it) {
                    int v = tid + it * 256, r = v >> 3, j = v & 7;
                    uint32_t d = sb + nxtOff + 2u * ABYTES + (uint32_t)(r * RS + j * 16);
                    cp16(d,                    W1hi + (size_t)(n0 + r) * D_ + k0 + j * 8);
                    cp16(d + (uint32_t)ABYTES, W1lo + (size_t)(n0 + r) * D_ + k0 + j * 8);
                }
                asm volatile("cp.async.commit_group;" ::: "memory");
#pragma unroll
                for (int it = 0; it < 8; ++it) {
                    int v = tid + it * 256, r = v >> 4, c4 = v & 15;
                    areg[it] = *reinterpret_cast<const float4*>(
                        V + (size_t)(row0 + r) * D_ + k0 + c4 * 4);
                }
            }

            // ---- compute 4 x k16 from current buffers ----
            const uint32_t Ah = sb + curOff;
            const uint32_t Bh = sb + curOff + 2u * ABYTES;
#pragma unroll
            for (int kk = 0; kk < 4; ++kk) {
                const uint32_t kb = (uint32_t)(kk * 32);
                uint32_t ah[4][4];
#pragma unroll
                for (int mt = 0; mt < 4; ++mt)
                    ldsm4(ah[mt], Ah + aoff + (uint32_t)(mt * 16 * RS) + kb);
                uint32_t bh[2][4];
#pragma unroll
                for (int p = 0; p < 2; ++p)
                    ldsm4(bh[p], Bh + boff + (uint32_t)(p * 16 * RS) + kb);
                // hi * hi
#pragma unroll
                for (int mt = 0; mt < 4; ++mt)
#pragma unroll
                    for (int nt = 0; nt < 4; ++nt)
                        mma16816(c[mt][nt], ah[mt],
                                 bh[nt >> 1][(nt & 1) * 2], bh[nt >> 1][(nt & 1) * 2 + 1]);
                // hi * lo
                uint32_t bl[2][4];
#pragma unroll
                for (int p = 0; p < 2; ++p)
                    ldsm4(bl[p], Bh + (uint32_t)ABYTES + boff + (uint32_t)(p * 16 * RS) + kb);
#pragma unroll
                for (int mt = 0; mt < 4; ++mt)
#pragma unroll
                    for (int nt = 0; nt < 4; ++nt)
                        mma16816(c[mt][nt], ah[mt],
                                 bl[nt >> 1][(nt & 1) * 2], bl[nt >> 1][(nt & 1) * 2 + 1]);
                // lo * hi
                uint32_t al[4][4];
#pragma unroll
                for (int mt = 0; mt < 4; ++mt)
                    ldsm4(al[mt], Ah + (uint32_t)ABYTES + aoff + (uint32_t)(mt * 16 * RS) + kb);
#pragma unroll
                for (int mt = 0; mt < 4; ++mt)
#pragma unroll
                    for (int nt = 0; nt < 4; ++nt)
                        mma16816(c[mt][nt], al[mt],
                                 bh[nt >> 1][(nt & 1) * 2], bh[nt >> 1][(nt & 1) * 2 + 1]);
            }

            if (s < 11) {
#pragma unroll
                for (int it = 0; it < 8; ++it) {
                    int v = tid + it * 256, r = v >> 4, c4 = v & 15;
                    float f[4] = {areg[it].x, areg[it].y, areg[it].z, areg[it].w};
                    unsigned short hs[4], ls[4];
#pragma unroll
                    for (int j = 0; j < 4; ++j) {
                        __nv_bfloat16 h = __float2bfloat16(f[j]);
                        __nv_bfloat16 l = __float2bfloat16(f[j] - __bfloat162float(h));
                        hs[j] = __bfloat16_as_ushort(h); ls[j] = __bfloat16_as_ushort(l);
                    }
                    uint2 hp = make_uint2((uint32_t)hs[0] | ((uint32_t)hs[1] << 16),
                                          (uint32_t)hs[2] | ((uint32_t)hs[3] << 16));
                    uint2 lp = make_uint2((uint32_t)ls[0] | ((uint32_t)ls[1] << 16),
                                          (uint32_t)ls[2] | ((uint32_t)ls[3] << 16));
                    char* base = sm + nxtOff + r * RS + c4 * 8;
                    *reinterpret_cast<uint2*>(base)          = hp;
                    *reinterpret_cast<uint2*>(base + ABYTES) = lp;
                }
                asm volatile("cp.async.wait_group 0;" ::: "memory");
            }
            __syncthreads();
        }

        // ---- epilogue: accumulate partial g into gs ----
#pragma unroll
        for (int mt = 0; mt < 4; ++mt) {
            float s0 = 0.0f, s1 = 0.0f;
#pragma unroll
            for (int nt = 0; nt < 4; ++nt) {
                int n = nc * 128 + wn * 32 + nt * 8 + (lane & 3) * 2;
                float w0 = w2s[n],     w1v = w2s[n + 1];
                float q0 = b1s[n],     q1  = b1s[n + 1];
                s0 += w0 * tanhf(c[mt][nt][0] + q0) + w1v * tanhf(c[mt][nt][1] + q1);
                s1 += w0 * tanhf(c[mt][nt][2] + q0) + w1v * tanhf(c[mt][nt][3] + q1);
            }
            s0 += __shfl_xor_sync(0xffffffffu, s0, 1);
            s0 += __shfl_xor_sync(0xffffffffu, s0, 2);
            s1 += __shfl_xor_sync(0xffffffffu, s1, 1);
            s1 += __shfl_xor_sync(0xffffffffu, s1, 2);
            if ((lane & 3) == 0) {
                int m = wm * 64 + mt * 16 + (lane >> 2);
                gs[wn * 128 + m]     += s0;
                gs[wn * 128 + m + 8] += s1;
            }
        }
    }

    __syncthreads();
    if (tid < 128)
        g_buf[row0 + tid] = gs[tid] + gs[128 + tid] + gs[256 + tid] + gs[384 + tid]
                          + B2[0];
}

// ---------------------------------------------------------------------------
// attn_kernel: per-batch attention + classifier, V tile cached in smem.
// Uses ms == 1/61 identity to skip the first softmax.
// ---------------------------------------------------------------------------
#define AOFF_V   0
#define AOFF_TH  (S_ * D_ * 4)              // 187392
#define AOFF_TT  (AOFF_TH + D_ * 4)
#define AOFF_ENT (AOFF_TT + D_ * 4)
#define AOFF_SCH (AOFF_ENT + 2 * D_ * 4)
#define AOFF_SCT (AOFF_SCH + 256)
#define AOFF_G   (AOFF_SCT + 256)
#define AOFF_WH  (AOFF_G + 256)
#define AOFF_WT  (AOFF_WH + 256)
#define ATTN_SMEM (AOFF_WT + 256)           // 200960

__global__ __launch_bounds__(256, 1)
void attn_kernel(const float* __restrict__ T,
                 const float* __restrict__ V,
                 const int*   __restrict__ ids,
                 const float* __restrict__ CW,
                 const float* __restrict__ CB,
                 float*       __restrict__ out)
{
    extern __shared__ char sm[];
    float* Vs   = reinterpret_cast<float*>(sm + AOFF_V);
    float* Th   = reinterpret_cast<float*>(sm + AOFF_TH);
    float* Tt   = reinterpret_cast<float*>(sm + AOFF_TT);
    float* ent  = reinterpret_cast<float*>(sm + AOFF_ENT);
    float* sc_h = reinterpret_cast<float*>(sm + AOFF_SCH);
    float* sc_t = reinterpret_cast<float*>(sm + AOFF_SCT);
    float* gsA  = reinterpret_cast<float*>(sm + AOFF_G);
    float* wh   = reinterpret_cast<float*>(sm + AOFF_WH);
    float* wt   = reinterpret_cast<float*>(sm + AOFF_WT);
    __shared__ int hidx, tidx;

    const int b   = blockIdx.x;
    const int tid = threadIdx.x;
    const int warp = tid >> 5, lane = tid & 31;

    // V tile -> smem (read V from DRAM exactly once)
    const float4* vsrc = reinterpret_cast<const float4*>(V + (size_t)b * S_ * D_);
    for (int i = tid; i < S_ * D_ / 4; i += 256)
        reinterpret_cast<float4*>(Vs)[i] = vsrc[i];

    if (tid == 0) { hidx = 0; tidx = 0; }
    __syncthreads();

    if (tid < S_) {
        int id = ids[b * S_ + tid];
        if (id == HEAD_TOK) hidx = tid;
        if (id == TAIL_TOK) tidx = tid;
        gsA[tid] = g_buf[b * S_ + tid];
    }
    __syncthreads();

    const int hq = hidx, tq = tidx;
    for (int d = tid; d < D_; d += 256) {
        Th[d] = T[((size_t)b * S_ + hq) * D_ + d];
        Tt[d] = T[((size_t)b * S_ + tq) * D_ + d];
    }
    __syncthreads();

    // raw scores for the two needed query rows (from smem V)
    for (int k = warp; k < S_; k += 8) {
        const float* vk = Vs + k * D_;
        float sh = 0.0f, st = 0.0f;
        for (int d = lane; d < D_; d += 32) {
            float v = vk[d];
            sh = fmaf(Th[d], v, sh);
            st = fmaf(Tt[d], v, st);
        }
#pragma unroll
        for (int o = 16; o; o >>= 1) {
            sh += __shfl_xor_sync(0xffffffffu, sh, o);
            st += __shfl_xor_sync(0xffffffffu, st, o);
        }
        if (lane == 0) { sc_h[k] = sh; sc_t[k] = st; }
    }
    __syncthreads();

    // gated softmax: a = (scores*(1-g) + g/61) / sqrt(768)
    if (warp < 2) {
        const float* sc = warp ? sc_t : sc_h;
        float*       w  = warp ? wt   : wh;
        const float scale = sqrtf((float)D_);
        const float inv61 = 1.0f / (float)S_;

        int k0 = lane, k1 = lane + 32;
        float a0 = -1e30f, a1 = -1e30f;
        if (k0 < S_) a0 = (sc[k0] * (1.0f - gsA[k0]) + gsA[k0] * inv61) / scale;
        if (k1 < S_) a1 = (sc[k1] * (1.0f - gsA[k1]) + gsA[k1] * inv61) / scale;
        float m = fmaxf(a0, a1);
#pragma unroll
        for (int o = 16; o; o >>= 1) m = fmaxf(m, __shfl_xor_sync(0xffffffffu, m, o));
        float e0 = (k0 < S_) ? expf(a0 - m) : 0.0f;
        float e1 = (k1 < S_) ? expf(a1 - m) : 0.0f;
        float s = e0 + e1;
#pragma unroll
        for (int o = 16; o; o >>= 1) s += __shfl_xor_sync(0xffffffffu, s, o);
        float inv = 1.0f / s;
        if (k0 < S_) w[k0] = e0 * inv;
        if (k1 < S_) w[k1] = e1 * inv;
    }
    __syncthreads();

    // entity vector: weighted sums over V keys (from smem V)
    for (int d = tid; d < D_; d += 256) {
        float ah = 0.0f, at = 0.0f;
        const float* vb = Vs + d;
#pragma unroll 4
        for (int k = 0; k < S_; ++k) {
            float v = vb[k * D_];
            ah = fmaf(wh[k], v, ah);
            at = fmaf(wt[k], v, at);
        }
        ent[d]      = ah;
        ent[D_ + d] = at;
    }
    __syncthreads();

    // classifier
    for (int l = warp; l < L_; l += 8) {
        const float* cw = CW + (size_t)l * (2 * D_);
        float s = 0.0f;
        for (int d = lane; d < 2 * D_; d += 32)
            s = fmaf(cw[d], ent[d], s);
#pragma unroll
        for (int o = 16; o; o >>= 1) s += __shfl_xor_sync(0xffffffffu, s, o);
        if (lane == 0) out[(size_t)b * L_ + l] = s + CB[l];
    }
}

// ---------------------------------------------------------------------------
extern "C" void kernel_launch(void* const* d_in, const int* in_sizes, int n_in,
                              void* d_out, int out_size)
{
    const float* T_recon = (const float*)d_in[0];
    const float* V_recon = (const float*)d_in[1];
    const int*   ids     = (const int*)  d_in[2];
    const float* fc1_w   = (const float*)d_in[3];
    const float* fc1_b   = (const float*)d_in[4];
    const float* fc2_w   = (const float*)d_in[5];
    const float* fc2_b   = (const float*)d_in[6];
    const float* clf_w   = (const float*)d_in[7];
    const float* clf_b   = (const float*)d_in[8];
    float* out = (float*)d_out;

    static bool attr_set = false;
    cudaFuncSetAttribute(gate_kernel,
                         cudaFuncAttributeMaxDynamicSharedMemorySize, GATE_SMEM);
    cudaFuncSetAttribute(attn_kernel,
                         cudaFuncAttributeMaxDynamicSharedMemorySize, ATTN_SMEM);
    (void)attr_set;

    prep_kernel<<<H_ * D_ / 4 / 256, 256>>>(fc1_w);
    gate_kernel<<<MTOT / 128, 256, GATE_SMEM>>>(V_recon, fc1_b, fc2_w, fc2_b);
    attn_kernel<<<B_, 256, ATTN_SMEM>>>(T_recon, V_recon, ids, clf_w, clf_b, out);
}